// round 14
// baseline (speedup 1.0000x reference)
#include <cuda_runtime.h>
#include <cuda_fp16.h>
#include <mma.h>
#include <cstdint>
#include <cstddef>

using namespace nvcuda;

// ---------------- problem constants ----------------
#define B_   64
#define T_   2048
#define C_   512
#define M_   80
#define P_   128
#define A_   128
#define H_   1024
#define FH_  4096         // 4*H
#define K1A  640          // P + C   (attention LSTM Wih cols)
#define KTA  1664         // P + C + H
#define K1D  1536         // H + C   (decoder  LSTM Wih cols)
#define KTD  2560         // H + C + H
#define NT2  67           // 31-stride tiling of T=2048 (32-row tiles)
#define Q_BLKS 16         // q-GEMM blocks fused into the att launch
#define DEC_BLKS 256      // decoder-GEMM blocks fused into the att launch

#define LO_SCALE   1024.0f
#define LO_INV     0.0009765625f

// att smem: 32-row fp16 tile + single Wm buffer -> 3 blocks/SM
#define TILE_PITCH 520                     // halves; 1040B row stride
#define TILE_BYTES (32 * TILE_PITCH * 2)   // 33280
#define WMBUF_BYTES (128 * 136 * 2)        // 34816
#define ATT_SMEM (TILE_BYTES + WMBUF_BYTES)   // 68096
#define SKEYS_OFF TILE_BYTES               // sKeys [32][132] f32 = 16896 B
#define SRED_OFF  (TILE_BYTES + 20480)     // sRed  [2][512]  f32 = 4096 B

// gemm_body smem layout (within any >=46080-byte buffer)
#define GB_XH 0
#define GB_XL 18432
#define GB_W  36864
#define GB_BYTES 46080

// output offsets (float32 elements), tuple order:
// x_dec[64,1536], ctx[64,512], w_new[64,2048], ah, ac, dh, dc (each 64x1024)
#define O_XDEC 0
#define O_CTX  98304
#define O_WNEW 131072
#define O_AH   262144
#define O_AC   327680
#define O_DH   393216
#define O_DC   458752

// ---------------- device scratch (no allocation allowed) ----------------
__device__ __half g_x1_hi[B_ * KTA];
__device__ __half g_x1_lo[B_ * KTA];
__device__ __half g_x2_hi[B_ * KTD];
__device__ __half g_x2_lo[B_ * KTD];
__device__ __half g_wm_h[A_ * C_];           // att_Wm fp16
__device__ float  g_gatesA[4 * B_ * FH_];    // attention LSTM partials (split-K x4)
__device__ float  g_gatesD[3 * B_ * FH_];    // decoder LSTM partials (ah|hdec|ctx)
__device__ float  g_ah[B_ * H_];             // zoneout-ed attention h (fp32)
__device__ float  g_q[4 * B_ * A_];          // q partials (split-K x4)
__device__ int    g_qflag;                   // q completion counter
__device__ float  g_ctx_part[NT2 * B_ * C_];

// ---------------- helpers ----------------
__device__ __forceinline__ float sigm(float x) { return 1.f / (1.f + expf(-x)); }

__device__ __forceinline__ float tanh_ap(float x) {
    float r; asm("tanh.approx.f32 %0, %1;" : "=f"(r) : "f"(x)); return r;
}
__device__ __forceinline__ float ex2_ap(float x) {
    float r; asm("ex2.approx.f32 %0, %1;" : "=f"(r) : "f"(x)); return r;
}
__device__ __forceinline__ float sigm_ap(float x) {
    return 1.f / (1.f + ex2_ap(-1.44269504f * x));
}

__device__ __forceinline__ void split_hl(float v, __half& hi, __half& lo) {
    hi = __float2half_rn(v);
    lo = __float2half_rn((v - __half2float(hi)) * LO_SCALE);
}

__device__ __forceinline__ uint32_t rotl32(uint32_t x, int d) {
    return (x << d) | (x >> (32 - d));
}

__device__ __forceinline__ void cp16(uint32_t dst, const void* src) {
    asm volatile("cp.async.cg.shared.global [%0], [%1], 16;" :: "r"(dst), "l"(src));
}

// Threefry-2x32, 20 rounds (canonical)
__device__ void tf2x32(uint32_t k0, uint32_t k1, uint32_t x0, uint32_t x1,
                       uint32_t& o0, uint32_t& o1) {
    uint32_t k2 = k0 ^ k1 ^ 0x1BD11BDAu;
    x0 += k0; x1 += k1;
    x0 += x1; x1 = rotl32(x1, 13); x1 ^= x0;
    x0 += x1; x1 = rotl32(x1, 15); x1 ^= x0;
    x0 += x1; x1 = rotl32(x1, 26); x1 ^= x0;
    x0 += x1; x1 = rotl32(x1,  6); x1 ^= x0;
    x0 += k1; x1 += k2 + 1u;
    x0 += x1; x1 = rotl32(x1, 17); x1 ^= x0;
    x0 += x1; x1 = rotl32(x1, 29); x1 ^= x0;
    x0 += x1; x1 = rotl32(x1, 16); x1 ^= x0;
    x0 += x1; x1 = rotl32(x1, 24); x1 ^= x0;
    x0 += k2; x1 += k0 + 2u;
    x0 += x1; x1 = rotl32(x1, 13); x1 ^= x0;
    x0 += x1; x1 = rotl32(x1, 15); x1 ^= x0;
    x0 += x1; x1 = rotl32(x1, 26); x1 ^= x0;
    x0 += x1; x1 = rotl32(x1,  6); x1 ^= x0;
    x0 += k0; x1 += k1 + 3u;
    x0 += x1; x1 = rotl32(x1, 17); x1 ^= x0;
    x0 += x1; x1 = rotl32(x1, 29); x1 ^= x0;
    x0 += x1; x1 = rotl32(x1, 16); x1 ^= x0;
    x0 += x1; x1 = rotl32(x1, 24); x1 ^= x0;
    x0 += k1; x1 += k2 + 4u;
    x0 += x1; x1 = rotl32(x1, 13); x1 ^= x0;
    x0 += x1; x1 = rotl32(x1, 15); x1 ^= x0;
    x0 += x1; x1 = rotl32(x1, 26); x1 ^= x0;
    x0 += x1; x1 = rotl32(x1,  6); x1 ^= x0;
    x0 += k2; x1 += k0 + 5u;
    o0 = x0; o1 = x1;
}

// jax_threefry_partitionable=True: split -> full 64-bit output per counter
__device__ __forceinline__ void derive_keys(uint32_t& a0, uint32_t& a1,
                                            uint32_t& b0, uint32_t& b1) {
    tf2x32(0u, 42u, 0u, 0u, a0, a1);   // dk1
    tf2x32(0u, 42u, 0u, 1u, b0, b1);   // dk2
}

// partitionable random_bits(32): element i -> counter (0, i), bits = o0 ^ o1
__device__ __forceinline__ bool keep_mask(uint32_t k0, uint32_t k1, int i) {
    uint32_t o0, o1;
    tf2x32(k0, k1, 0u, (uint32_t)i, o0, o1);
    return ((o0 ^ o1) >> 31) == 0u;
}

// ================= K1: prenet + hi/lo staging =================
__global__ void prep_kernel(const float* __restrict__ x,
                            const float* __restrict__ ctx_att,
                            const float* __restrict__ h_att_h,
                            const float* __restrict__ h_dec_h,
                            const float* __restrict__ pre_W1, const float* __restrict__ pre_b1,
                            const float* __restrict__ pre_W2, const float* __restrict__ pre_b2,
                            const float* __restrict__ att_Wm) {
    int bid = blockIdx.x, tid = threadIdx.x;
    if (bid < 64) {
        __shared__ float sx[M_];
        __shared__ float sh1[P_];
        int b = bid;
        if (tid < M_) sx[tid] = x[b * M_ + tid];
        __syncthreads();
        uint32_t d10, d11, d20, d21;
        derive_keys(d10, d11, d20, d21);
        {   // layer 1 + dropout(dk1)
            int p = tid;
            float s = pre_b1[p];
            const float* wr = pre_W1 + p * M_;
            #pragma unroll
            for (int m = 0; m < M_; m++) s += wr[m] * sx[m];
            s = fmaxf(s, 0.f);
            s = keep_mask(d10, d11, b * P_ + p) ? s * 2.f : 0.f;
            sh1[p] = s;
        }
        __syncthreads();
        {   // layer 2 + dropout(dk2)
            int p = tid;
            float s = pre_b2[p];
            const float* wr = pre_W2 + p * P_;
            #pragma unroll 8
            for (int k = 0; k < P_; k++) s += wr[k] * sh1[k];
            s = fmaxf(s, 0.f);
            s = keep_mask(d20, d21, b * P_ + p) ? s * 2.f : 0.f;
            __half hi, lo; split_hl(s, hi, lo);
            g_x1_hi[b * KTA + p] = hi;
            g_x1_lo[b * KTA + p] = lo;
        }
    } else if (bid < 128) {
        int b = bid - 64;
        for (int j = tid; j < C_; j += 128) {
            __half hi, lo; split_hl(ctx_att[b * C_ + j], hi, lo);
            g_x1_hi[b * KTA + P_ + j] = hi;
            g_x1_lo[b * KTA + P_ + j] = lo;
        }
    } else if (bid < 192) {
        int b = bid - 128;
        for (int j = tid; j < H_; j += 128) {
            __half hi, lo; split_hl(h_att_h[b * H_ + j], hi, lo);
            g_x1_hi[b * KTA + K1A + j] = hi;
            g_x1_lo[b * KTA + K1A + j] = lo;
        }
    } else if (bid < 256) {
        int b = bid - 192;
        for (int j = tid; j < H_; j += 128) {
            __half hi, lo; split_hl(h_dec_h[b * H_ + j], hi, lo);
            g_x2_hi[b * KTD + K1D + j] = hi;
            g_x2_lo[b * KTD + K1D + j] = lo;
        }
    } else {
        int base = (bid - 256) * 512;
        for (int j = tid; j < 512; j += 128)
            g_wm_h[base + j] = __float2half(att_Wm[base + j]);
    }
}

// ================= shared GEMM body =========================================
// Computes G[64, n0:n0+32] partial over chunk range [c_beg, c_end).
// Needs >=256 threads; mma on warps 0..7.
template<int KTOT, int K1, int K2>
__device__ __forceinline__ void gemm_body(char* smb,
                                          const __half* __restrict__ Xhi,
                                          const __half* __restrict__ Xlo,
                                          const float* __restrict__ W1,
                                          const float* __restrict__ W2,
                                          float* __restrict__ G, int ld_g,
                                          int n0, int c_beg, int c_end) {
    __half* sXh = (__half*)(smb + GB_XH);    // [2][64*72]
    __half* sXl = (__half*)(smb + GB_XL);    // [2][64*72]
    __half* sW  = (__half*)(smb + GB_W);     // [2][32*72]
    int tid = threadIdx.x;
    bool ldr = tid < 256;
    int w = tid >> 5;
    int warp_m = w & 3;
    int warp_n = (w >> 2) & 1;

    int xrow0 = tid >> 3,            xc8 = tid & 7;
    int xrow1 = ((tid & 255) + 256) >> 3;
    int wrow0 = tid >> 4,            wc4 = tid & 15;
    int wrow1 = ((tid & 255) + 256) >> 4;

    wmma::fragment<wmma::accumulator, 16, 16, 16, float> acc_h, acc_l;
    wmma::fill_fragment(acc_h, 0.f);
    wmma::fill_fragment(acc_l, 0.f);

    uint4  rXh0, rXh1, rXl0, rXl1;
    float4 rW0, rW1;

    auto fetch = [&](int c0) {
        size_t o0 = (size_t)xrow0 * KTOT + c0 + xc8 * 8;
        size_t o1 = (size_t)xrow1 * KTOT + c0 + xc8 * 8;
        rXh0 = *(const uint4*)(Xhi + o0);
        rXh1 = *(const uint4*)(Xhi + o1);
        rXl0 = *(const uint4*)(Xlo + o0);
        rXl1 = *(const uint4*)(Xlo + o1);
        const float* Wsrc; int ld;
        if (c0 < K1) { Wsrc = W1 + c0; ld = K1; }
        else         { Wsrc = W2 + (c0 - K1); ld = K2; }
        rW0 = *(const float4*)(Wsrc + (size_t)(n0 + wrow0) * ld + wc4 * 4);
        rW1 = *(const float4*)(Wsrc + (size_t)(n0 + wrow1) * ld + wc4 * 4);
    };

    auto commit = [&](int bsel) {
        __half* xh = sXh + bsel * (64 * 72);
        __half* xl = sXl + bsel * (64 * 72);
        __half* wb = sW  + bsel * (32 * 72);
        *(uint4*)(&xh[xrow0 * 72 + xc8 * 8]) = rXh0;
        *(uint4*)(&xh[xrow1 * 72 + xc8 * 8]) = rXh1;
        *(uint4*)(&xl[xrow0 * 72 + xc8 * 8]) = rXl0;
        *(uint4*)(&xl[xrow1 * 72 + xc8 * 8]) = rXl1;
        __half2 a01 = __floats2half2_rn(rW0.x, rW0.y);
        __half2 a23 = __floats2half2_rn(rW0.z, rW0.w);
        __half2 b01 = __floats2half2_rn(rW1.x, rW1.y);
        __half2 b23 = __floats2half2_rn(rW1.z, rW1.w);
        *(__half2*)(&wb[wrow0 * 72 + wc4 * 4])     = a01;
        *(__half2*)(&wb[wrow0 * 72 + wc4 * 4 + 2]) = a23;
        *(__half2*)(&wb[wrow1 * 72 + wc4 * 4])     = b01;
        *(__half2*)(&wb[wrow1 * 72 + wc4 * 4 + 2]) = b23;
    };

    if (ldr) fetch(c_beg * 64);
    for (int cc = c_beg; cc < c_end; cc++) {
        int bsel = cc & 1;
        if (ldr) commit(bsel);
        __syncthreads();
        if (ldr && cc + 1 < c_end) fetch((cc + 1) * 64);
        if (w < 8) {
            const __half* xh = sXh + bsel * (64 * 72);
            const __half* xl = sXl + bsel * (64 * 72);
            const __half* wb = sW  + bsel * (32 * 72);
            #pragma unroll
            for (int kk = 0; kk < 4; kk++) {
                wmma::fragment<wmma::matrix_a, 16, 16, 16, __half, wmma::row_major> ah, al;
                wmma::fragment<wmma::matrix_b, 16, 16, 16, __half, wmma::col_major> bh;
                wmma::load_matrix_sync(ah, xh + warp_m * 16 * 72 + kk * 16, 72);
                wmma::load_matrix_sync(al, xl + warp_m * 16 * 72 + kk * 16, 72);
                wmma::load_matrix_sync(bh, wb + warp_n * 16 * 72 + kk * 16, 72);
                wmma::mma_sync(acc_h, ah, bh, acc_h);
                wmma::mma_sync(acc_l, al, bh, acc_l);
            }
        }
    }
    if (w < 8) {
        #pragma unroll
        for (int i = 0; i < acc_h.num_elements; i++)
            acc_h.x[i] += LO_INV * acc_l.x[i];
        wmma::store_matrix_sync(G + (size_t)(warp_m * 16) * ld_g + n0 + warp_n * 16,
                                acc_h, ld_g, wmma::mem_row_major);
    }
}

// ================= K2/K7: standalone LSTM GEMM (runtime split-K) ===========
template<int KTOT, int K1, int K2>
__global__ void lstm_gemm(const __half* __restrict__ Xhi,
                          const __half* __restrict__ Xlo,
                          const float* __restrict__ W1,
                          const float* __restrict__ W2,
                          float* __restrict__ G,
                          int c0, int c1, int slab0) {
    __shared__ __align__(16) char buf[GB_BYTES];
    int ny = gridDim.y, y = blockIdx.y;
    int cb = c0 + ((c1 - c0) * y) / ny;
    int ce = c0 + ((c1 - c0) * (y + 1)) / ny;
    gemm_body<KTOT, K1, K2>(buf, Xhi, Xlo, W1, W2,
                            G + (size_t)(slab0 + y) * B_ * FH_, FH_,
                            blockIdx.x * 32, cb, ce);
}

// ================= K3/K8: LSTM pointwise + zoneout (sums nslabs partials) ==
__global__ void lstm_point(const float* __restrict__ G, int nslabs,
                           const float* __restrict__ bih, const float* __restrict__ bhh,
                           const float* __restrict__ h_old, const float* __restrict__ c_old,
                           float* __restrict__ out_h, float* __restrict__ out_c,
                           float* __restrict__ gh_f32,
                           __half* __restrict__ xh_dst,
                           __half* __restrict__ xl_dst,
                           int xh_stride, int xh_off,
                           float* __restrict__ xdec_dst) {
    int e = blockIdx.x * blockDim.x + threadIdx.x;
    if (gh_f32 && e == 0) g_qflag = 0;        // reset q counter before att launch
    int b = e >> 10, a = e & 1023;
    float gi = bih[a]        + bhh[a];
    float gf = bih[1024 + a] + bhh[1024 + a];
    float gg = bih[2048 + a] + bhh[2048 + a];
    float go = bih[3072 + a] + bhh[3072 + a];
    #pragma unroll 4
    for (int s = 0; s < 4; s++) {
        if (s >= nslabs) break;
        const float* g = G + (size_t)s * B_ * FH_ + (size_t)b * FH_;
        gi += g[a]; gf += g[1024 + a]; gg += g[2048 + a]; go += g[3072 + a];
    }
    float c0 = c_old[e], h0 = h_old[e];
    float cn = sigm(gf) * c0 + sigm(gi) * tanhf(gg);
    float hn = sigm(go) * tanhf(cn);
    float hz = 0.9f * hn + 0.1f * h0;
    float cz = 0.9f * cn + 0.1f * c0;
    out_h[e] = hz; out_c[e] = cz;
    if (gh_f32)  gh_f32[e] = hz;
    if (xh_dst) {
        __half hi, lo; split_hl(hz, hi, lo);
        xh_dst[b * xh_stride + xh_off + a] = hi;
        xl_dst[b * xh_stride + xh_off + a] = lo;
    }
    if (xdec_dst) xdec_dst[b * 1536 + a] = hz;
}

// ================= K5: attention + overlapped q GEMM + decoder GEMM ========
// 256 threads, 3 blocks/SM. 32-row tiles; 4 mma warps with 2x2 blocking.
__global__ __launch_bounds__(256, 3)
void att_kernel(const float* __restrict__ memory,
                const float* __restrict__ w_att,
                const float* __restrict__ att_v,
                float* __restrict__ out_wnew,
                const float* __restrict__ drn_Wih,
                const float* __restrict__ drn_Whh,
                const float* __restrict__ att_Wq,
                const float* __restrict__ att_bq,
                const float* __restrict__ att_bm) {
    extern __shared__ char sm[];
    int tid = threadIdx.x;
    int bid = blockIdx.x;

    if (bid < Q_BLKS) {
        int y = bid >> 2;
        gemm_body<KTD, 1024, 1024>(sm, g_x2_hi, g_x2_lo, att_Wq, att_Wq,
                                   g_q + (size_t)y * B_ * A_, A_,
                                   (bid & 3) * 32, 4 * y, 4 * y + 4);
        __syncthreads();
        if (tid == 0) {
            __threadfence();
            atomicAdd(&g_qflag, 1);
        }
        return;
    }

    if (bid < Q_BLKS + DEC_BLKS) {
        int db = bid - Q_BLKS;
        int y = db >> 7;                        // 0: ah chunks, 1: h_dec chunks
        int n0 = (db & 127) * 32;
        if (y == 0)
            gemm_body<KTD, K1D, H_>(sm, g_x2_hi, g_x2_lo, drn_Wih, drn_Whh,
                                    g_gatesD, FH_, n0, 0, 16);
        else
            gemm_body<KTD, K1D, H_>(sm, g_x2_hi, g_x2_lo, drn_Wih, drn_Whh,
                                    g_gatesD + (size_t)B_ * FH_, FH_, n0, 24, 40);
        return;
    }

    int id = bid - (Q_BLKS + DEC_BLKS);
    int bx = id % NT2;                         // tile index
    int b  = id / NT2;                         // batch row

    __half* sTile = (__half*)sm;                       // [32][520]
    __half* sWm   = (__half*)(sm + TILE_BYTES);        // [128][136]
    float*  sKeys = (float*)(sm + SKEYS_OFF);          // [32][132] aliases sWm
    float*  sRed  = (float*)(sm + SRED_OFF);           // [2][512]  aliases sWm tail
    __shared__ float sP[32], sWn[32], sS[128], sV[128];

    int w = tid >> 5;                          // 8 warps
    int t0 = 31 * bx;

    // acc[2][2]: m-tile i (rows 16i), na-tile (2w + j); mma on warps 0..3
    wmma::fragment<wmma::accumulator, 16, 16, 16, float> acc[2][2];
    #pragma unroll
    for (int i = 0; i < 2; i++)
        #pragma unroll
        for (int j = 0; j < 2; j++) wmma::fill_fragment(acc[i][j], 0.f);

    const float* memb = memory + (size_t)b * T_ * C_;
    uint32_t wbase = (uint32_t)__cvta_generic_to_shared(sm + TILE_BYTES);

    auto issueWm = [&](int cc) {
        #pragma unroll
        for (int i = 0; i < 8; i++) {
            int lin = i * 256 + tid;
            int a = lin >> 4, c8 = lin & 15;
            cp16(wbase + (uint32_t)(a * 136 + c8 * 8) * 2,
                 g_wm_h + a * C_ + cc * 128 + c8 * 8);
        }
        asm volatile("cp.async.commit_group;");
    };

    auto loadConv = [&](int cc) {              // tile chunk: load+convert+store
        #pragma unroll
        for (int i = 0; i < 4; i++) {
            int lin = i * 256 + tid;           // 0..1023
            int r = lin >> 5, c4 = lin & 31;   // 32 rows x 32 float4
            int gr = t0 + r; if (gr > T_ - 1) gr = T_ - 1;
            float4 v = *(const float4*)(memb + (size_t)gr * C_ + cc * 128 + c4 * 4);
            __half2 h01 = __floats2half2_rn(v.x, v.y);
            __half2 h23 = __floats2half2_rn(v.z, v.w);
            __half* dst = sTile + r * TILE_PITCH + cc * 128 + c4 * 4;
            *(__half2*)(dst)     = h01;
            *(__half2*)(dst + 2) = h23;
        }
    };

    // ---- phase 1: keys = tile @ Wm^T ----
    issueWm(0);
    for (int cc = 0; cc < 4; cc++) {
        loadConv(cc);
        asm volatile("cp.async.wait_group 0;");
        __syncthreads();                       // tile chunk + Wm(cc) visible
        if (w < 4) {
            #pragma unroll
            for (int kk = 0; kk < 8; kk++) {
                wmma::fragment<wmma::matrix_a, 16, 16, 16, __half, wmma::row_major> af0, af1;
                wmma::fragment<wmma::matrix_b, 16, 16, 16, __half, wmma::col_major> bf0, bf1;
                wmma::load_matrix_sync(af0, sTile + cc * 128 + kk * 16, TILE_PITCH);
                wmma::load_matrix_sync(af1, sTile + 16 * TILE_PITCH + cc * 128 + kk * 16,
                                       TILE_PITCH);
                wmma::load_matrix_sync(bf0, sWm + (w * 2) * 16 * 136 + kk * 16, 136);
                wmma::load_matrix_sync(bf1, sWm + (w * 2 + 1) * 16 * 136 + kk * 16, 136);
                wmma::mma_sync(acc[0][0], af0, bf0, acc[0][0]);
                wmma::mma_sync(acc[0][1], af0, bf1, acc[0][1]);
                wmma::mma_sync(acc[1][0], af1, bf0, acc[1][0]);
                wmma::mma_sync(acc[1][1], af1, bf1, acc[1][1]);
            }
        }
        __syncthreads();                       // sWm consumed before refill
        if (cc < 3) issueWm(cc + 1);
    }

    // ---- wait for the fused q blocks, then build sS/sV ----
    if (tid == 0) {
        int v;
        do {
            asm volatile("ld.acquire.gpu.global.s32 %0, [%1];"
                         : "=r"(v) : "l"(&g_qflag) : "memory");
            if (v < Q_BLKS) __nanosleep(128);
        } while (v < Q_BLKS);
    }
    if (tid < 128) {
        float s = att_bq[tid] + att_bm[tid];
        #pragma unroll
        for (int y = 0; y < 4; y++) s += g_q[(size_t)y * B_ * A_ + b * A_ + tid];
        sS[tid] = s;
        sV[tid] = att_v[tid];
    }

    // ---- phase 2: e -> p -> w_new (sKeys aliases sWm; safe post-sync) ----
    if (w < 4) {
        #pragma unroll
        for (int i = 0; i < 2; i++)
            #pragma unroll
            for (int j = 0; j < 2; j++)
                wmma::store_matrix_sync(sKeys + (i * 16) * 132 + (w * 2 + j) * 16,
                                        acc[i][j], 132, wmma::mem_row_major);
    }
    __syncthreads();
    {
        int t = tid >> 3, q = tid & 7;         // 32 rows x 8 threads, 16 cols each
        float s = 0.f;
        const float* kr = sKeys + t * 132 + q * 16;
        const float* ss = sS + q * 16;
        const float* vv = sV + q * 16;
        #pragma unroll
        for (int j = 0; j < 16; j++) s += vv[j] * tanh_ap(kr[j] + ss[j]);
        s += __shfl_xor_sync(0xffffffffu, s, 1);
        s += __shfl_xor_sync(0xffffffffu, s, 2);
        s += __shfl_xor_sync(0xffffffffu, s, 4);
        if (q == 0) sP[t] = sigm_ap(s);
    }
    __syncthreads();
    if (tid < 32) {
        int r = tid, t = t0 + r;
        float wn_v = 0.f; bool valid = false;
        if (t < T_) {
            if (r == 0) {
                if (bx == 0) { wn_v = w_att[b * T_] * sP[0]; valid = true; }
            } else {
                wn_v = w_att[b * T_ + t] * sP[r]
                     + w_att[b * T_ + t - 1] * (1.f - sP[r - 1]);
                valid = true;
            }
        }
        sWn[r] = valid ? wn_v : 0.f;
        if (valid) out_wnew[b * T_ + t] = wn_v;
    }
    __syncthreads();

    // ---- phase 3: ctx partial, vectorized (4 cols/thread, 2-way row split) --
    {
        int part = tid >> 7;                   // 0..1 -> rows 16*part..
        int cq = tid & 127;                    // 4-col group
        float a0 = 0.f, a1 = 0.f, a2 = 0.f, a3 = 0.f;
        const __half* base = sTile + cq * 4;
        #pragma unroll
        for (int r = part * 16; r < part * 16 + 16; r++) {
            float wv = sWn[r];
            uint2 u = *(const uint2*)(base + r * TILE_PITCH);
            __half2 h01 = *(__half2*)&u.x;
            __half2 h23 = *(__half2*)&u.y;
            a0 += wv * __low2float(h01);  a1 += wv * __high2float(h01);
            a2 += wv * __low2float(h23);  a3 += wv * __high2float(h23);
        }
        float4 st = make_float4(a0, a1, a2, a3);
        *(float4*)(sRed + (part * 128 + cq) * 4) = st;
    }
    __syncthreads();
    if (tid < 128) {
        float4 x0 = *(float4*)(sRed + tid * 4);
        float4 x1 = *(float4*)(sRed + (128 + tid) * 4);
        float4 s = make_float4(x0.x + x1.x, x0.y + x1.y, x0.z + x1.z, x0.w + x1.w);
        *(float4*)(g_ctx_part + ((size_t)bx * B_ + b) * C_ + tid * 4) = s;
    }
}

// ================= K6: ctx reduce + staging =================
__global__ void ctx_reduce(float* __restrict__ out_ctx, float* __restrict__ out_xdec) {
    int e = blockIdx.x * blockDim.x + threadIdx.x;   // < 32768
    int b = e >> 9, c = e & 511;
    float s = 0.f;
    #pragma unroll 8
    for (int i = 0; i < NT2; i++)
        s += g_ctx_part[((size_t)i * B_ + b) * C_ + c];
    out_ctx[e] = s;
    out_xdec[b * 1536 + 1024 + c] = s;
    __half hi, lo; split_hl(s, hi, lo);
    g_x2_hi[b * KTD + H_ + c] = hi;
    g_x2_lo[b * KTD + H_ + c] = lo;
}

// ================= launch =================
extern "C" void kernel_launch(void* const* d_in, const int* in_sizes, int n_in,
                              void* d_out, int out_size) {
    const float* x        = (const float*)d_in[0];
    const float* w_att    = (const float*)d_in[1];
    const float* ctx_att  = (const float*)d_in[2];
    const float* h_att_h  = (const float*)d_in[3];
    const float* h_att_c  = (const float*)d_in[4];
    const float* h_dec_h  = (const float*)d_in[5];
    const float* h_dec_c  = (const float*)d_in[6];
    const float* memory   = (const float*)d_in[7];
    const float* pre_W1   = (const float*)d_in[9];
    const float* pre_b1   = (const float*)d_in[10];
    const float* pre_W2   = (const float*)d_in[11];
    const float* pre_b2   = (const float*)d_in[12];
    const float* att_Wq   = (const float*)d_in[13];
    const float* att_bq   = (const float*)d_in[14];
    const float* att_Wm   = (const float*)d_in[15];
    const float* att_bm   = (const float*)d_in[16];
    const float* att_v    = (const float*)d_in[17];
    const float* arn_Wih  = (const float*)d_in[18];
    const float* arn_Whh  = (const float*)d_in[19];
    const float* arn_bih  = (const float*)d_in[20];
    const float* arn_bhh  = (const float*)d_in[21];
    const float* drn_Wih  = (const float*)d_in[22];
    const float* drn_Whh  = (const float*)d_in[23];
    const float* drn_bih  = (const float*)d_in[24];
    const float* drn_bhh  = (const float*)d_in[25];
    float* out = (float*)d_out;

    __half* x1h; cudaGetSymbolAddress((void**)&x1h, g_x1_hi);
    __half* x1l; cudaGetSymbolAddress((void**)&x1l, g_x1_lo);
    __half* x2h; cudaGetSymbolAddress((void**)&x2h, g_x2_hi);
    __half* x2l; cudaGetSymbolAddress((void**)&x2l, g_x2_lo);
    float*  gatesA; cudaGetSymbolAddress((void**)&gatesA, g_gatesA);
    float*  gatesD; cudaGetSymbolAddress((void**)&gatesD, g_gatesD);
    float*  ahf;    cudaGetSymbolAddress((void**)&ahf, g_ah);

    cudaFuncSetAttribute(att_kernel, cudaFuncAttributeMaxDynamicSharedMemorySize, ATT_SMEM);

    // K1: prenet + hi/lo staging + Wm convert
    prep_kernel<<<384, 128>>>(x, ctx_att, h_att_h, h_dec_h,
                              pre_W1, pre_b1, pre_W2, pre_b2, att_Wm);
    // K2: attention LSTM gates (split-K x4, slabs 0..3)
    lstm_gemm<KTA, K1A, H_><<<dim3(128, 4), 256>>>(x1h, x1l, arn_Wih, arn_Whh,
                                                   gatesA, 0, 26, 0);
    // K3: attention LSTM pointwise -> ah, ac (+ stage ah, reset g_qflag)
    lstm_point<<<256, 256>>>(gatesA, 4, arn_bih, arn_bhh, h_att_h, h_att_c,
                             out + O_AH, out + O_AC, ahf, x2h, x2l, KTD, 0, nullptr);
    // K5: attention + overlapped q GEMM + decoder GEMM
    att_kernel<<<Q_BLKS + DEC_BLKS + NT2 * B_, 256, ATT_SMEM>>>(
        memory, w_att, att_v, out + O_WNEW, drn_Wih, drn_Whh,
        att_Wq, att_bq, att_bm);
    // K6: ctx reduce + staging
    ctx_reduce<<<128, 256>>>(out + O_CTX, out + O_XDEC);
    // K7: decoder GEMM ctx slice (chunks 16..23, slab 2)
    lstm_gemm<KTD, K1D, H_><<<dim3(128, 1), 256>>>(x2h, x2l, drn_Wih, drn_Whh,
                                                   gatesD, 16, 24, 2);
    // K8: decoder LSTM pointwise -> dh, dc (+ x_dec[:, :1024] = dh)
    lstm_point<<<256, 256>>>(gatesD, 3, drn_bih, drn_bhh, h_dec_h, h_dec_c,
                             out + O_DH, out + O_DC, nullptr, nullptr, nullptr, 0, 0,
                             out + O_XDEC);
    (void)in_sizes; (void)n_in; (void)out_size;
}

// round 15
// speedup vs baseline: 1.0507x; 1.0507x over previous
#include <cuda_runtime.h>
#include <cuda_fp16.h>
#include <mma.h>
#include <cstdint>
#include <cstddef>

using namespace nvcuda;

// ---------------- problem constants ----------------
#define B_   64
#define T_   2048
#define C_   512
#define M_   80
#define P_   128
#define A_   128
#define H_   1024
#define FH_  4096         // 4*H
#define K1A  640          // P + C   (attention LSTM Wih cols)
#define KTA  1664         // P + C + H
#define K1D  1536         // H + C   (decoder  LSTM Wih cols)
#define KTD  2560         // H + C + H
#define NT2  33           // 63-stride tiling of T=2048 (64-row tiles)
#define Q_BLKS 16         // q-GEMM blocks fused into the att launch
#define DEC_BLKS 256      // decoder-GEMM blocks fused into the att launch

#define LO_SCALE   1024.0f
#define LO_INV     0.0009765625f

// att_kernel smem layout (dynamic): 64-row tile + single Wm buffer
#define TILE_PITCH 520                     // halves; 1040B row stride
#define TILE_BYTES (64 * TILE_PITCH * 2)   // 66560
#define WMBUF_BYTES (128 * 136 * 2)        // 34816
#define ATT_SMEM (TILE_BYTES + WMBUF_BYTES)   // 101376 -> 2 blocks/SM

// gemm_body smem layout (within any >=46080-byte buffer)
#define GB_XH 0
#define GB_XL 18432
#define GB_W  36864
#define GB_BYTES 46080

// output offsets (float32 elements), tuple order:
// x_dec[64,1536], ctx[64,512], w_new[64,2048], ah, ac, dh, dc (each 64x1024)
#define O_XDEC 0
#define O_CTX  98304
#define O_WNEW 131072
#define O_AH   262144
#define O_AC   327680
#define O_DH   393216
#define O_DC   458752

// ---------------- device scratch (no allocation allowed) ----------------
__device__ __half g_x1_hi[B_ * KTA];
__device__ __half g_x1_lo[B_ * KTA];
__device__ __half g_x2_hi[B_ * KTD];
__device__ __half g_x2_lo[B_ * KTD];
__device__ __half g_wm_h[A_ * C_];           // att_Wm fp16
__device__ float  g_gatesA[4 * B_ * FH_];    // attention LSTM partials (split-K x4)
__device__ float  g_gatesD[3 * B_ * FH_];    // decoder LSTM partials (ah|hdec|ctx)
__device__ float  g_ah[B_ * H_];             // zoneout-ed attention h (fp32)
__device__ float  g_q[4 * B_ * A_];          // q partials (split-K x4)
__device__ int    g_qflag;                   // q completion counter
__device__ float  g_ctx_part[NT2 * B_ * C_];

// ---------------- helpers ----------------
__device__ __forceinline__ float sigm(float x) { return 1.f / (1.f + expf(-x)); }

__device__ __forceinline__ float tanh_ap(float x) {
    float r; asm("tanh.approx.f32 %0, %1;" : "=f"(r) : "f"(x)); return r;
}
__device__ __forceinline__ float ex2_ap(float x) {
    float r; asm("ex2.approx.f32 %0, %1;" : "=f"(r) : "f"(x)); return r;
}
__device__ __forceinline__ float sigm_ap(float x) {
    return 1.f / (1.f + ex2_ap(-1.44269504f * x));
}

__device__ __forceinline__ void split_hl(float v, __half& hi, __half& lo) {
    hi = __float2half_rn(v);
    lo = __float2half_rn((v - __half2float(hi)) * LO_SCALE);
}

__device__ __forceinline__ uint32_t rotl32(uint32_t x, int d) {
    return (x << d) | (x >> (32 - d));
}

__device__ __forceinline__ void cp16(uint32_t dst, const void* src) {
    asm volatile("cp.async.cg.shared.global [%0], [%1], 16;" :: "r"(dst), "l"(src));
}

// Threefry-2x32, 20 rounds (canonical)
__device__ void tf2x32(uint32_t k0, uint32_t k1, uint32_t x0, uint32_t x1,
                       uint32_t& o0, uint32_t& o1) {
    uint32_t k2 = k0 ^ k1 ^ 0x1BD11BDAu;
    x0 += k0; x1 += k1;
    x0 += x1; x1 = rotl32(x1, 13); x1 ^= x0;
    x0 += x1; x1 = rotl32(x1, 15); x1 ^= x0;
    x0 += x1; x1 = rotl32(x1, 26); x1 ^= x0;
    x0 += x1; x1 = rotl32(x1,  6); x1 ^= x0;
    x0 += k1; x1 += k2 + 1u;
    x0 += x1; x1 = rotl32(x1, 17); x1 ^= x0;
    x0 += x1; x1 = rotl32(x1, 29); x1 ^= x0;
    x0 += x1; x1 = rotl32(x1, 16); x1 ^= x0;
    x0 += x1; x1 = rotl32(x1, 24); x1 ^= x0;
    x0 += k2; x1 += k0 + 2u;
    x0 += x1; x1 = rotl32(x1, 13); x1 ^= x0;
    x0 += x1; x1 = rotl32(x1, 15); x1 ^= x0;
    x0 += x1; x1 = rotl32(x1, 26); x1 ^= x0;
    x0 += x1; x1 = rotl32(x1,  6); x1 ^= x0;
    x0 += k0; x1 += k1 + 3u;
    x0 += x1; x1 = rotl32(x1, 17); x1 ^= x0;
    x0 += x1; x1 = rotl32(x1, 29); x1 ^= x0;
    x0 += x1; x1 = rotl32(x1, 16); x1 ^= x0;
    x0 += x1; x1 = rotl32(x1, 24); x1 ^= x0;
    x0 += k1; x1 += k2 + 4u;
    x0 += x1; x1 = rotl32(x1, 13); x1 ^= x0;
    x0 += x1; x1 = rotl32(x1, 15); x1 ^= x0;
    x0 += x1; x1 = rotl32(x1, 26); x1 ^= x0;
    x0 += x1; x1 = rotl32(x1,  6); x1 ^= x0;
    x0 += k2; x1 += k0 + 5u;
    o0 = x0; o1 = x1;
}

// jax_threefry_partitionable=True: split -> full 64-bit output per counter
__device__ __forceinline__ void derive_keys(uint32_t& a0, uint32_t& a1,
                                            uint32_t& b0, uint32_t& b1) {
    tf2x32(0u, 42u, 0u, 0u, a0, a1);   // dk1
    tf2x32(0u, 42u, 0u, 1u, b0, b1);   // dk2
}

// partitionable random_bits(32): element i -> counter (0, i), bits = o0 ^ o1
__device__ __forceinline__ bool keep_mask(uint32_t k0, uint32_t k1, int i) {
    uint32_t o0, o1;
    tf2x32(k0, k1, 0u, (uint32_t)i, o0, o1);
    return ((o0 ^ o1) >> 31) == 0u;
}

// ================= K1: prenet + hi/lo staging =================
__global__ void prep_kernel(const float* __restrict__ x,
                            const float* __restrict__ ctx_att,
                            const float* __restrict__ h_att_h,
                            const float* __restrict__ h_dec_h,
                            const float* __restrict__ pre_W1, const float* __restrict__ pre_b1,
                            const float* __restrict__ pre_W2, const float* __restrict__ pre_b2,
                            const float* __restrict__ att_Wm) {
    int bid = blockIdx.x, tid = threadIdx.x;
    if (bid < 64) {
        __shared__ float sx[M_];
        __shared__ float sh1[P_];
        int b = bid;
        if (tid < M_) sx[tid] = x[b * M_ + tid];
        __syncthreads();
        uint32_t d10, d11, d20, d21;
        derive_keys(d10, d11, d20, d21);
        {   // layer 1 + dropout(dk1)
            int p = tid;
            float s = pre_b1[p];
            const float* wr = pre_W1 + p * M_;
            #pragma unroll
            for (int m = 0; m < M_; m++) s += wr[m] * sx[m];
            s = fmaxf(s, 0.f);
            s = keep_mask(d10, d11, b * P_ + p) ? s * 2.f : 0.f;
            sh1[p] = s;
        }
        __syncthreads();
        {   // layer 2 + dropout(dk2)
            int p = tid;
            float s = pre_b2[p];
            const float* wr = pre_W2 + p * P_;
            #pragma unroll 8
            for (int k = 0; k < P_; k++) s += wr[k] * sh1[k];
            s = fmaxf(s, 0.f);
            s = keep_mask(d20, d21, b * P_ + p) ? s * 2.f : 0.f;
            __half hi, lo; split_hl(s, hi, lo);
            g_x1_hi[b * KTA + p] = hi;
            g_x1_lo[b * KTA + p] = lo;
        }
    } else if (bid < 128) {
        int b = bid - 64;
        for (int j = tid; j < C_; j += 128) {
            __half hi, lo; split_hl(ctx_att[b * C_ + j], hi, lo);
            g_x1_hi[b * KTA + P_ + j] = hi;
            g_x1_lo[b * KTA + P_ + j] = lo;
        }
    } else if (bid < 192) {
        int b = bid - 128;
        for (int j = tid; j < H_; j += 128) {
            __half hi, lo; split_hl(h_att_h[b * H_ + j], hi, lo);
            g_x1_hi[b * KTA + K1A + j] = hi;
            g_x1_lo[b * KTA + K1A + j] = lo;
        }
    } else if (bid < 256) {
        int b = bid - 192;
        for (int j = tid; j < H_; j += 128) {
            __half hi, lo; split_hl(h_dec_h[b * H_ + j], hi, lo);
            g_x2_hi[b * KTD + K1D + j] = hi;
            g_x2_lo[b * KTD + K1D + j] = lo;
        }
    } else {
        int base = (bid - 256) * 512;
        for (int j = tid; j < 512; j += 128)
            g_wm_h[base + j] = __float2half(att_Wm[base + j]);
    }
}

// ================= shared GEMM body =========================================
// Computes G[64, n0:n0+32] partial over chunk range [c_beg, c_end).
// Works with >=256 threads: threads 256+ only participate in barriers.
template<int KTOT, int K1, int K2>
__device__ __forceinline__ void gemm_body(char* smb,
                                          const __half* __restrict__ Xhi,
                                          const __half* __restrict__ Xlo,
                                          const float* __restrict__ W1,
                                          const float* __restrict__ W2,
                                          float* __restrict__ G, int ld_g,
                                          int n0, int c_beg, int c_end) {
    __half* sXh = (__half*)(smb + GB_XH);    // [2][64*72]
    __half* sXl = (__half*)(smb + GB_XL);    // [2][64*72]
    __half* sW  = (__half*)(smb + GB_W);     // [2][32*72]
    int tid = threadIdx.x;
    bool ldr = tid < 256;
    int w = tid >> 5;
    int warp_m = w & 3;
    int warp_n = (w >> 2) & 1;

    int xrow0 = tid >> 3,            xc8 = tid & 7;
    int xrow1 = ((tid & 255) + 256) >> 3;
    int wrow0 = tid >> 4,            wc4 = tid & 15;
    int wrow1 = ((tid & 255) + 256) >> 4;

    wmma::fragment<wmma::accumulator, 16, 16, 16, float> acc_h, acc_l;
    wmma::fill_fragment(acc_h, 0.f);
    wmma::fill_fragment(acc_l, 0.f);

    uint4  rXh0, rXh1, rXl0, rXl1;
    float4 rW0, rW1;

    auto fetch = [&](int c0) {
        size_t o0 = (size_t)xrow0 * KTOT + c0 + xc8 * 8;
        size_t o1 = (size_t)xrow1 * KTOT + c0 + xc8 * 8;
        rXh0 = *(const uint4*)(Xhi + o0);
        rXh1 = *(const uint4*)(Xhi + o1);
        rXl0 = *(const uint4*)(Xlo + o0);
        rXl1 = *(const uint4*)(Xlo + o1);
        const float* Wsrc; int ld;
        if (c0 < K1) { Wsrc = W1 + c0; ld = K1; }
        else         { Wsrc = W2 + (c0 - K1); ld = K2; }
        rW0 = *(const float4*)(Wsrc + (size_t)(n0 + wrow0) * ld + wc4 * 4);
        rW1 = *(const float4*)(Wsrc + (size_t)(n0 + wrow1) * ld + wc4 * 4);
    };

    auto commit = [&](int bsel) {
        __half* xh = sXh + bsel * (64 * 72);
        __half* xl = sXl + bsel * (64 * 72);
        __half* wb = sW  + bsel * (32 * 72);
        *(uint4*)(&xh[xrow0 * 72 + xc8 * 8]) = rXh0;
        *(uint4*)(&xh[xrow1 * 72 + xc8 * 8]) = rXh1;
        *(uint4*)(&xl[xrow0 * 72 + xc8 * 8]) = rXl0;
        *(uint4*)(&xl[xrow1 * 72 + xc8 * 8]) = rXl1;
        __half2 a01 = __floats2half2_rn(rW0.x, rW0.y);
        __half2 a23 = __floats2half2_rn(rW0.z, rW0.w);
        __half2 b01 = __floats2half2_rn(rW1.x, rW1.y);
        __half2 b23 = __floats2half2_rn(rW1.z, rW1.w);
        *(__half2*)(&wb[wrow0 * 72 + wc4 * 4])     = a01;
        *(__half2*)(&wb[wrow0 * 72 + wc4 * 4 + 2]) = a23;
        *(__half2*)(&wb[wrow1 * 72 + wc4 * 4])     = b01;
        *(__half2*)(&wb[wrow1 * 72 + wc4 * 4 + 2]) = b23;
    };

    if (ldr) fetch(c_beg * 64);
    for (int cc = c_beg; cc < c_end; cc++) {
        int bsel = cc & 1;
        if (ldr) commit(bsel);
        __syncthreads();
        if (ldr && cc + 1 < c_end) fetch((cc + 1) * 64);
        if (w < 8) {
            const __half* xh = sXh + bsel * (64 * 72);
            const __half* xl = sXl + bsel * (64 * 72);
            const __half* wb = sW  + bsel * (32 * 72);
            #pragma unroll
            for (int kk = 0; kk < 4; kk++) {
                wmma::fragment<wmma::matrix_a, 16, 16, 16, __half, wmma::row_major> ah, al;
                wmma::fragment<wmma::matrix_b, 16, 16, 16, __half, wmma::col_major> bh;
                wmma::load_matrix_sync(ah, xh + warp_m * 16 * 72 + kk * 16, 72);
                wmma::load_matrix_sync(al, xl + warp_m * 16 * 72 + kk * 16, 72);
                wmma::load_matrix_sync(bh, wb + warp_n * 16 * 72 + kk * 16, 72);
                wmma::mma_sync(acc_h, ah, bh, acc_h);
                wmma::mma_sync(acc_l, al, bh, acc_l);
            }
        }
    }
    if (w < 8) {
        #pragma unroll
        for (int i = 0; i < acc_h.num_elements; i++)
            acc_h.x[i] += LO_INV * acc_l.x[i];
        wmma::store_matrix_sync(G + (size_t)(warp_m * 16) * ld_g + n0 + warp_n * 16,
                                acc_h, ld_g, wmma::mem_row_major);
    }
}

// ================= K2/K7: standalone LSTM GEMM (runtime split-K) ===========
template<int KTOT, int K1, int K2>
__global__ void lstm_gemm(const __half* __restrict__ Xhi,
                          const __half* __restrict__ Xlo,
                          const float* __restrict__ W1,
                          const float* __restrict__ W2,
                          float* __restrict__ G,
                          int c0, int c1, int slab0) {
    __shared__ __align__(16) char buf[GB_BYTES];
    int ny = gridDim.y, y = blockIdx.y;
    int cb = c0 + ((c1 - c0) * y) / ny;
    int ce = c0 + ((c1 - c0) * (y + 1)) / ny;
    gemm_body<KTOT, K1, K2>(buf, Xhi, Xlo, W1, W2,
                            G + (size_t)(slab0 + y) * B_ * FH_, FH_,
                            blockIdx.x * 32, cb, ce);
}

// ================= K3/K8: LSTM pointwise + zoneout (sums nslabs partials) ==
__global__ void lstm_point(const float* __restrict__ G, int nslabs,
                           const float* __restrict__ bih, const float* __restrict__ bhh,
                           const float* __restrict__ h_old, const float* __restrict__ c_old,
                           float* __restrict__ out_h, float* __restrict__ out_c,
                           float* __restrict__ gh_f32,
                           __half* __restrict__ xh_dst,
                           __half* __restrict__ xl_dst,
                           int xh_stride, int xh_off,
                           float* __restrict__ xdec_dst) {
    int e = blockIdx.x * blockDim.x + threadIdx.x;
    if (gh_f32 && e == 0) g_qflag = 0;        // reset q counter before att launch
    int b = e >> 10, a = e & 1023;
    float gi = bih[a]        + bhh[a];
    float gf = bih[1024 + a] + bhh[1024 + a];
    float gg = bih[2048 + a] + bhh[2048 + a];
    float go = bih[3072 + a] + bhh[3072 + a];
    #pragma unroll 4
    for (int s = 0; s < 4; s++) {
        if (s >= nslabs) break;
        const float* g = G + (size_t)s * B_ * FH_ + (size_t)b * FH_;
        gi += g[a]; gf += g[1024 + a]; gg += g[2048 + a]; go += g[3072 + a];
    }
    float c0 = c_old[e], h0 = h_old[e];
    float cn = sigm(gf) * c0 + sigm(gi) * tanhf(gg);
    float hn = sigm(go) * tanhf(cn);
    float hz = 0.9f * hn + 0.1f * h0;
    float cz = 0.9f * cn + 0.1f * c0;
    out_h[e] = hz; out_c[e] = cz;
    if (gh_f32)  gh_f32[e] = hz;
    if (xh_dst) {
        __half hi, lo; split_hl(hz, hi, lo);
        xh_dst[b * xh_stride + xh_off + a] = hi;
        xl_dst[b * xh_stride + xh_off + a] = lo;
    }
    if (xdec_dst) xdec_dst[b * 1536 + a] = hz;
}

// ================= K5: attention + overlapped q GEMM + decoder GEMM ========
// 1D grid: [0, Q_BLKS) q GEMM (signals g_qflag); [Q_BLKS, Q_BLKS+DEC_BLKS)
// decoder-GEMM independent chunks; rest = attention tiles (spin on g_qflag
// only at phase 2, ~10us into their execution).
__global__ __launch_bounds__(512, 2)
void att_kernel(const float* __restrict__ memory,
                const float* __restrict__ w_att,
                const float* __restrict__ att_v,
                float* __restrict__ out_wnew,
                const float* __restrict__ drn_Wih,
                const float* __restrict__ drn_Whh,
                const float* __restrict__ att_Wq,
                const float* __restrict__ att_bq,
                const float* __restrict__ att_bm) {
    extern __shared__ char sm[];
    int tid = threadIdx.x;
    int bid = blockIdx.x;

    if (bid < Q_BLKS) {
        // q partial: n-tile (bid&3), K-chunks [4y, 4y+4) of ah (cols 0..1023 of x2)
        int y = bid >> 2;
        gemm_body<KTD, 1024, 1024>(sm, g_x2_hi, g_x2_lo, att_Wq, att_Wq,
                                   g_q + (size_t)y * B_ * A_, A_,
                                   (bid & 3) * 32, 4 * y, 4 * y + 4);
        __syncthreads();
        if (tid == 0) {
            __threadfence();
            atomicAdd(&g_qflag, 1);
        }
        return;
    }

    if (bid < Q_BLKS + DEC_BLKS) {
        int db = bid - Q_BLKS;
        int y = db >> 7;                        // 0: ah chunks, 1: h_dec chunks
        int n0 = (db & 127) * 32;
        if (y == 0)
            gemm_body<KTD, K1D, H_>(sm, g_x2_hi, g_x2_lo, drn_Wih, drn_Whh,
                                    g_gatesD, FH_, n0, 0, 16);
        else
            gemm_body<KTD, K1D, H_>(sm, g_x2_hi, g_x2_lo, drn_Wih, drn_Whh,
                                    g_gatesD + (size_t)B_ * FH_, FH_, n0, 24, 40);
        return;
    }

    int id = bid - (Q_BLKS + DEC_BLKS);
    int bx = id % NT2;                         // tile index
    int b  = id / NT2;                         // batch row

    __half* sTile = (__half*)sm;                       // [64][520]
    __half* sWm   = (__half*)(sm + TILE_BYTES);        // [128][136]
    float*  sKeys = (float*)(sm + TILE_BYTES);         // aliases sWm post-mma
    __shared__ float sP[64], sWn[64], sS[128], sV[128];

    int w = tid >> 5;
    int wm = w & 3;
    int wng = w >> 2;
    int t0 = 63 * bx;

    wmma::fragment<wmma::accumulator, 16, 16, 16, float> acc[2];
    #pragma unroll
    for (int j = 0; j < 2; j++) wmma::fill_fragment(acc[j], 0.f);

    const float* memb = memory + (size_t)b * T_ * C_;
    uint32_t wbase = (uint32_t)__cvta_generic_to_shared(sm + TILE_BYTES);

    float4 rT[4];

    auto issueWm = [&](int cc) {
        #pragma unroll
        for (int i = 0; i < 4; i++) {
            int lin = i * 512 + tid;
            int a = lin >> 4, c8 = lin & 15;
            cp16(wbase + (uint32_t)(a * 136 + c8 * 8) * 2,
                 g_wm_h + a * C_ + cc * 128 + c8 * 8);
        }
        asm volatile("cp.async.commit_group;");
    };

    auto fetchT = [&](int cc) {
        #pragma unroll
        for (int i = 0; i < 4; i++) {
            int lin = i * 512 + tid;
            int r = lin >> 5, c4 = lin & 31;
            int gr = t0 + r; if (gr > T_ - 1) gr = T_ - 1;
            rT[i] = *(const float4*)(memb + (size_t)gr * C_ + cc * 128 + c4 * 4);
        }
    };

    auto commitT = [&](int cc) {
        #pragma unroll
        for (int i = 0; i < 4; i++) {
            int lin = i * 512 + tid;
            int r = lin >> 5, c4 = lin & 31;
            __half2 h01 = __floats2half2_rn(rT[i].x, rT[i].y);
            __half2 h23 = __floats2half2_rn(rT[i].z, rT[i].w);
            __half* dst = sTile + r * TILE_PITCH + cc * 128 + c4 * 4;
            *(__half2*)(dst)     = h01;
            *(__half2*)(dst + 2) = h23;
        }
    };

    // ---- phase 1: keys = tile @ Wm^T ----
    issueWm(0);
    fetchT(0);
    for (int cc = 0; cc < 4; cc++) {
        commitT(cc);
        asm volatile("cp.async.wait_group 0;");
        __syncthreads();
        if (cc < 3) fetchT(cc + 1);
        #pragma unroll
        for (int kk = 0; kk < 8; kk++) {
            wmma::fragment<wmma::matrix_a, 16, 16, 16, __half, wmma::row_major> af;
            wmma::load_matrix_sync(af, sTile + (wm * 16) * TILE_PITCH + cc * 128 + kk * 16,
                                   TILE_PITCH);
            #pragma unroll
            for (int j = 0; j < 2; j++) {
                int na = wng * 2 + j;
                wmma::fragment<wmma::matrix_b, 16, 16, 16, __half, wmma::col_major> bf;
                wmma::load_matrix_sync(bf, sWm + (na * 16) * 136 + kk * 16, 136);
                wmma::mma_sync(acc[j], af, bf, acc[j]);
            }
        }
        __syncthreads();
        if (cc < 3) issueWm(cc + 1);
    }

    // ---- wait for the fused q blocks, then build sS/sV ----
    if (tid == 0) {
        int v;
        do {
            asm volatile("ld.acquire.gpu.global.s32 %0, [%1];"
                         : "=r"(v) : "l"(&g_qflag) : "memory");
            if (v < Q_BLKS) __nanosleep(128);
        } while (v < Q_BLKS);
    }
    __syncthreads();
    if (tid < 128) {
        float s = att_bq[tid] + att_bm[tid];
        #pragma unroll
        for (int y = 0; y < 4; y++) s += g_q[(size_t)y * B_ * A_ + b * A_ + tid];
        sS[tid] = s;
        sV[tid] = att_v[tid];
    }

    // ---- phase 2: e -> p -> w_new ----
    #pragma unroll
    for (int j = 0; j < 2; j++)
        wmma::store_matrix_sync(sKeys + (wm * 16) * 132 + (wng * 2 + j) * 16, acc[j],
                                132, wmma::mem_row_major);
    __syncthreads();
    {
        int t = tid >> 3, q = tid & 7;
        float s = 0.f;
        const float* kr = sKeys + t * 132 + q * 16;
        const float* ss = sS + q * 16;
        const float* vv = sV + q * 16;
        #pragma unroll
        for (int j = 0; j < 16; j++) s += vv[j] * tanh_ap(kr[j] + ss[j]);
        s += __shfl_xor_sync(0xffffffffu, s, 1);
        s += __shfl_xor_sync(0xffffffffu, s, 2);
        s += __shfl_xor_sync(0xffffffffu, s, 4);
        if (q == 0) sP[t] = sigm_ap(s);
    }
    __syncthreads();
    if (tid < 64) {
        int r = tid, t = t0 + r;
        float wn_v = 0.f; bool valid = false;
        if (t < T_) {
            if (r == 0) {
                if (bx == 0) { wn_v = w_att[b * T_] * sP[0]; valid = true; }
            } else {
                wn_v = w_att[b * T_ + t] * sP[r]
                     + w_att[b * T_ + t - 1] * (1.f - sP[r - 1]);
                valid = true;
            }
        }
        sWn[r] = valid ? wn_v : 0.f;
        if (valid) out_wnew[b * T_ + t] = wn_v;
    }
    __syncthreads();

    // ---- phase 3: ctx partial, vectorized (128 threads x 4 cols, uint2) ----
    if (tid < 128) {
        const __half* base = sTile + tid * 4;
        float a0 = 0.f, a1 = 0.f, a2 = 0.f, a3 = 0.f;
        #pragma unroll 8
        for (int r = 0; r < 64; r++) {
            float wv = sWn[r];
            uint2 u = *(const uint2*)(base + r * TILE_PITCH);
            __half2 h01 = *(__half2*)&u.x;
            __half2 h23 = *(__half2*)&u.y;
            a0 += wv * __low2float(h01);  a1 += wv * __high2float(h01);
            a2 += wv * __low2float(h23);  a3 += wv * __high2float(h23);
        }
        *(float4*)(g_ctx_part + ((size_t)bx * B_ + b) * C_ + tid * 4) =
            make_float4(a0, a1, a2, a3);
    }
}

// ================= K6: ctx reduce + staging =================
__global__ void ctx_reduce(float* __restrict__ out_ctx, float* __restrict__ out_xdec) {
    int e = blockIdx.x * blockDim.x + threadIdx.x;   // < 32768
    int b = e >> 9, c = e & 511;
    float s = 0.f;
    #pragma unroll
    for (int i = 0; i < NT2; i++)
        s += g_ctx_part[((size_t)i * B_ + b) * C_ + c];
    out_ctx[e] = s;
    out_xdec[b * 1536 + 1024 + c] = s;
    __half hi, lo; split_hl(s, hi, lo);
    g_x2_hi[b * KTD + H_ + c] = hi;
    g_x2_lo[b * KTD + H_ + c] = lo;
}

// ================= launch =================
extern "C" void kernel_launch(void* const* d_in, const int* in_sizes, int n_in,
                              void* d_out, int out_size) {
    const float* x        = (const float*)d_in[0];
    const float* w_att    = (const float*)d_in[1];
    const float* ctx_att  = (const float*)d_in[2];
    const float* h_att_h  = (const float*)d_in[3];
    const float* h_att_c  = (const float*)d_in[4];
    const float* h_dec_h  = (const float*)d_in[5];
    const float* h_dec_c  = (const float*)d_in[6];
    const float* memory   = (const float*)d_in[7];
    const float* pre_W1   = (const float*)d_in[9];
    const float* pre_b1   = (const float*)d_in[10];
    const float* pre_W2   = (const float*)d_in[11];
    const float* pre_b2   = (const float*)d_in[12];
    const float* att_Wq   = (const float*)d_in[13];
    const float* att_bq   = (const float*)d_in[14];
    const float* att_Wm   = (const float*)d_in[15];
    const float* att_bm   = (const float*)d_in[16];
    const float* att_v    = (const float*)d_in[17];
    const float* arn_Wih  = (const float*)d_in[18];
    const float* arn_Whh  = (const float*)d_in[19];
    const float* arn_bih  = (const float*)d_in[20];
    const float* arn_bhh  = (const float*)d_in[21];
    const float* drn_Wih  = (const float*)d_in[22];
    const float* drn_Whh  = (const float*)d_in[23];
    const float* drn_bih  = (const float*)d_in[24];
    const float* drn_bhh  = (const float*)d_in[25];
    float* out = (float*)d_out;

    __half* x1h; cudaGetSymbolAddress((void**)&x1h, g_x1_hi);
    __half* x1l; cudaGetSymbolAddress((void**)&x1l, g_x1_lo);
    __half* x2h; cudaGetSymbolAddress((void**)&x2h, g_x2_hi);
    __half* x2l; cudaGetSymbolAddress((void**)&x2l, g_x2_lo);
    float*  gatesA; cudaGetSymbolAddress((void**)&gatesA, g_gatesA);
    float*  gatesD; cudaGetSymbolAddress((void**)&gatesD, g_gatesD);
    float*  ahf;    cudaGetSymbolAddress((void**)&ahf, g_ah);

    cudaFuncSetAttribute(att_kernel, cudaFuncAttributeMaxDynamicSharedMemorySize, ATT_SMEM);

    // K1: prenet + hi/lo staging + Wm convert
    prep_kernel<<<384, 128>>>(x, ctx_att, h_att_h, h_dec_h,
                              pre_W1, pre_b1, pre_W2, pre_b2, att_Wm);
    // K2: attention LSTM gates (split-K x4, slabs 0..3)
    lstm_gemm<KTA, K1A, H_><<<dim3(128, 4), 256>>>(x1h, x1l, arn_Wih, arn_Whh,
                                                   gatesA, 0, 26, 0);
    // K3: attention LSTM pointwise -> ah, ac (+ stage ah, reset g_qflag)
    lstm_point<<<256, 256>>>(gatesA, 4, arn_bih, arn_bhh, h_att_h, h_att_c,
                             out + O_AH, out + O_AC, ahf, x2h, x2l, KTD, 0, nullptr);
    // K5: attention + overlapped q GEMM + decoder GEMM
    att_kernel<<<Q_BLKS + DEC_BLKS + NT2 * B_, 512, ATT_SMEM>>>(
        memory, w_att, att_v, out + O_WNEW, drn_Wih, drn_Whh,
        att_Wq, att_bq, att_bm);
    // K6: ctx reduce + staging
    ctx_reduce<<<128, 256>>>(out + O_CTX, out + O_XDEC);
    // K7: decoder GEMM ctx slice (chunks 16..23, slab 2)
    lstm_gemm<KTD, K1D, H_><<<dim3(128, 1), 256>>>(x2h, x2l, drn_Wih, drn_Whh,
                                                   gatesD, 16, 24, 2);
    // K8: decoder LSTM pointwise -> dh, dc (+ x_dec[:, :1024] = dh)
    lstm_point<<<256, 256>>>(gatesD, 3, drn_bih, drn_bhh, h_dec_h, h_dec_c,
                             out + O_DH, out + O_DC, nullptr, nullptr, nullptr, 0, 0,
                             out + O_XDEC);
    (void)in_sizes; (void)n_in; (void)out_size;
}